// round 6
// baseline (speedup 1.0000x reference)
#include <cuda_runtime.h>
#include <cuda_bf16.h>
#include <math.h>
#include <stdint.h>

// ---------------------------------------------------------------------------
// Problem constants
// ---------------------------------------------------------------------------
#define BATCH 4
#define SEQ   2048
#define DMODEL 1024
#define NHEAD 16
#define HDIM  64
#define ROWS  (BATCH * SEQ)          // 8192
#define EPS   1e-5f

// ---------------------------------------------------------------------------
// Scratch buffers (static device globals: allocation-free per harness rules)
// ---------------------------------------------------------------------------
__device__ float g_ln [ROWS * DMODEL];        // 32 MB  (reused ln1 & ln2)
__device__ float g_qkv[ROWS * 3 * DMODEL];    // 96 MB
__device__ float g_y  [ROWS * DMODEL];        // 32 MB  attention output
__device__ float g_x1 [ROWS * DMODEL];        // 32 MB  residual after attn
__device__ float g_h  [ROWS * 4 * DMODEL];    // 128 MB MLP hidden
// tf32-pre-rounded weights
__device__ float g_wa [DMODEL * 3 * DMODEL];  // 12 MB
__device__ float g_wo [DMODEL * DMODEL];      // 4 MB
__device__ float g_wf [DMODEL * 4 * DMODEL];  // 16 MB
__device__ float g_wp [4 * DMODEL * DMODEL];  // 16 MB

// ---------------------------------------------------------------------------
// tf32 round helper (rna). Result is an fp32 bit pattern with low 13 bits 0.
// ---------------------------------------------------------------------------
__device__ __forceinline__ unsigned f2tf32(float f) {
    unsigned r;
    asm("cvt.rna.tf32.f32 %0, %1;" : "=r"(r) : "f"(f));
    return r;
}
__device__ __forceinline__ float roundtf32(float f) {
    return __uint_as_float(f2tf32(f));
}

// Pre-round a weight matrix to tf32 (once per launch). n4 = #float4 elements.
__global__ __launch_bounds__(256) void round_tf32_kernel(
    const float* __restrict__ in, float* __restrict__ out, int n4)
{
    int i = blockIdx.x * blockDim.x + threadIdx.x;
    if (i < n4) {
        float4 v = reinterpret_cast<const float4*>(in)[i];
        v.x = roundtf32(v.x); v.y = roundtf32(v.y);
        v.z = roundtf32(v.z); v.w = roundtf32(v.w);
        reinterpret_cast<float4*>(out)[i] = v;
    }
}

// ---------------------------------------------------------------------------
// LayerNorm: one block per row (D=1024), 256 threads, float4 per thread.
// Output rounded to tf32 (consumed only by GEMM A operands).
// ---------------------------------------------------------------------------
__device__ __forceinline__ float warp_sum(float v) {
#pragma unroll
    for (int o = 16; o > 0; o >>= 1) v += __shfl_xor_sync(0xffffffffu, v, o);
    return v;
}

__global__ __launch_bounds__(256) void ln_kernel(
    const float* __restrict__ x,
    const float* __restrict__ g,
    const float* __restrict__ b,
    float* __restrict__ out)
{
    const int row = blockIdx.x;
    const int tid = threadIdx.x;
    const float4 v = reinterpret_cast<const float4*>(x + (size_t)row * DMODEL)[tid];

    float s  = v.x + v.y + v.z + v.w;
    float ss = v.x*v.x + v.y*v.y + v.z*v.z + v.w*v.w;
    s  = warp_sum(s);
    ss = warp_sum(ss);

    __shared__ float red0[8], red1[8];
    const int wid = tid >> 5, lane = tid & 31;
    if (lane == 0) { red0[wid] = s; red1[wid] = ss; }
    __syncthreads();
    float ts = 0.f, tss = 0.f;
#pragma unroll
    for (int w = 0; w < 8; w++) { ts += red0[w]; tss += red1[w]; }

    const float mean = ts * (1.0f / DMODEL);
    const float var  = tss * (1.0f / DMODEL) - mean * mean;
    const float rstd = rsqrtf(var + EPS);

    const float4 gv = reinterpret_cast<const float4*>(g)[tid];
    const float4 bv = reinterpret_cast<const float4*>(b)[tid];
    float4 o;
    o.x = roundtf32((v.x - mean) * rstd * gv.x + bv.x);
    o.y = roundtf32((v.y - mean) * rstd * gv.y + bv.y);
    o.z = roundtf32((v.z - mean) * rstd * gv.z + bv.z);
    o.w = roundtf32((v.w - mean) * rstd * gv.w + bv.w);
    reinterpret_cast<float4*>(out + (size_t)row * DMODEL)[tid] = o;
}

// ---------------------------------------------------------------------------
// TF32 tensor-core GEMM: C[M,N] = A[M,K] @ B[K,N] (+ epilogue)
// CTA tile 128x128, BK=16, 256 threads (8 warps as 2x4 -> 64x32 warp tiles).
// 3-stage cp.async pipeline (2 tiles in flight). Operands pre-rounded to
// tf32 bit patterns, so the mainloop has ZERO cvt instructions.
// EPI: 0 = none, 1 = +res, 2 = gelu(acc + bias) [output tf32-rounded],
//      3 = acc + bias + res
// ---------------------------------------------------------------------------
__device__ __forceinline__ float gelu_tanh(float x) {
    const float c0 = 0.7978845608028654f;  // sqrt(2/pi)
    const float c1 = 0.044715f;
    float t = tanhf(c0 * (x + c1 * x * x * x));
    return 0.5f * x * (1.0f + t);
}

__device__ __forceinline__ void ldsm4(unsigned& r0, unsigned& r1,
                                      unsigned& r2, unsigned& r3, uint32_t a) {
    asm volatile("ldmatrix.sync.aligned.m8n8.x4.shared.b16 {%0,%1,%2,%3}, [%4];"
                 : "=r"(r0), "=r"(r1), "=r"(r2), "=r"(r3) : "r"(a));
}

__device__ __forceinline__ void mma_tf32(float* c,
                                         unsigned a0, unsigned a1,
                                         unsigned a2, unsigned a3,
                                         unsigned b0, unsigned b1) {
    asm volatile(
        "mma.sync.aligned.m16n8k8.row.col.f32.tf32.tf32.f32 "
        "{%0,%1,%2,%3}, {%4,%5,%6,%7}, {%8,%9}, {%0,%1,%2,%3};"
        : "+f"(c[0]), "+f"(c[1]), "+f"(c[2]), "+f"(c[3])
        : "r"(a0), "r"(a1), "r"(a2), "r"(a3), "r"(b0), "r"(b1));
}

#define AS_STRIDE 20
#define BS_STRIDE 132
#define A_ELEMS   (128 * AS_STRIDE)
#define B_ELEMS   (16 * BS_STRIDE)
#define GEMM_SMEM (3 * (A_ELEMS + B_ELEMS) * (int)sizeof(float))   // 56064 B

template <int EPI>
__global__ __launch_bounds__(256, 2) void tf32_gemm(
    int M, int N, int K,
    const float* __restrict__ A,
    const float* __restrict__ B,
    const float* __restrict__ bias,
    const float* __restrict__ res,
    float* __restrict__ C)
{
    extern __shared__ float smp[];
    float* sB = smp + 3 * A_ELEMS;
    const uint32_t sA_u = (uint32_t)__cvta_generic_to_shared(smp);
    const uint32_t sB_u = (uint32_t)__cvta_generic_to_shared(sB);

    const int tid  = threadIdx.x;
    const int lane = tid & 31;
    const int wid  = tid >> 5;
    const int m_w  = (wid >> 2) * 64;   // warp M origin (0 or 64)
    const int n_w  = (wid & 3) * 32;    // warp N origin

    // gmem -> smem thread mapping
    const int aRow  = tid >> 2;          // 0..63 (+64 second)
    const int aCol  = (tid & 3) * 4;
    const int bRowK = tid >> 5;          // 0..7  (+8 second)
    const int bColN = (tid & 31) * 4;

    const float* Ag = A + (size_t)(blockIdx.y * 128) * K;
    const float* Bg = B + (size_t)blockIdx.x * 128;

    float acc[4][4][4];
#pragma unroll
    for (int i = 0; i < 4; i++)
#pragma unroll
        for (int j = 0; j < 4; j++)
#pragma unroll
            for (int q = 0; q < 4; q++) acc[i][j][q] = 0.f;

    // per-thread ldmatrix lane mapping (constant)
    const int lr  = lane & 7;
    const int lm8 = ((lane >> 3) & 1) * 8;
    const int lc4 = (lane >> 4) * 4;

    const int nk = K >> 4;

#define LOAD_STAGE(KT, ST)                                                        \
    do {                                                                          \
        const float* a0p = Ag + (size_t)aRow * K + (KT) * 16 + aCol;              \
        uint32_t d0 = sA_u + (uint32_t)((ST) * A_ELEMS + aRow * AS_STRIDE + aCol) * 4u; \
        asm volatile("cp.async.cg.shared.global [%0], [%1], 16;"                  \
                     :: "r"(d0), "l"(a0p));                                       \
        asm volatile("cp.async.cg.shared.global [%0], [%1], 16;"                  \
                     :: "r"(d0 + 64u * AS_STRIDE * 4u), "l"(a0p + (size_t)64 * K)); \
        const float* b0p = Bg + (size_t)((KT) * 16 + bRowK) * N + bColN;          \
        uint32_t e0 = sB_u + (uint32_t)((ST) * B_ELEMS + bRowK * BS_STRIDE + bColN) * 4u; \
        asm volatile("cp.async.cg.shared.global [%0], [%1], 16;"                  \
                     :: "r"(e0), "l"(b0p));                                       \
        asm volatile("cp.async.cg.shared.global [%0], [%1], 16;"                  \
                     :: "r"(e0 + 8u * BS_STRIDE * 4u), "l"(b0p + (size_t)8 * N)); \
        asm volatile("cp.async.commit_group;");                                   \
    } while (0)

    LOAD_STAGE(0, 0);
    LOAD_STAGE(1, 1);

    int st = 0, ld = 2;
    for (int kt = 0; kt < nk; kt++) {
        if (kt + 2 < nk) {
            LOAD_STAGE(kt + 2, ld);
            asm volatile("cp.async.wait_group 2;");
        } else if (kt + 1 < nk) {
            asm volatile("cp.async.wait_group 1;");
        } else {
            asm volatile("cp.async.wait_group 0;");
        }
        __syncthreads();

        const uint32_t aBase = sA_u +
            (uint32_t)(st * A_ELEMS + (m_w + lr + lm8) * AS_STRIDE + lc4) * 4u;
        const float* bp = sB + st * B_ELEMS + (lane & 3) * BS_STRIDE
                        + n_w + (lane >> 2);

#pragma unroll
        for (int ks = 0; ks < 2; ks++) {
            const int k8 = ks * 8;
            unsigned afr[4][4];
#pragma unroll
            for (int mf = 0; mf < 4; mf++)
                ldsm4(afr[mf][0], afr[mf][1], afr[mf][2], afr[mf][3],
                      aBase + (uint32_t)(mf * 16 * AS_STRIDE + k8) * 4u);
            unsigned bfr[4][2];
#pragma unroll
            for (int nf = 0; nf < 4; nf++) {
                bfr[nf][0] = __float_as_uint(bp[k8 * BS_STRIDE + nf * 8]);
                bfr[nf][1] = __float_as_uint(bp[(k8 + 4) * BS_STRIDE + nf * 8]);
            }
#pragma unroll
            for (int mf = 0; mf < 4; mf++)
#pragma unroll
                for (int nf = 0; nf < 4; nf++)
                    mma_tf32(acc[mf][nf],
                             afr[mf][0], afr[mf][1], afr[mf][2], afr[mf][3],
                             bfr[nf][0], bfr[nf][1]);
        }
        __syncthreads();
        st++; if (st == 3) st = 0;
        ld++; if (ld == 3) ld = 0;
    }
#undef LOAD_STAGE

    // ---------------- epilogue ----------------
    const int row0 = blockIdx.y * 128 + m_w;
    const int col0 = blockIdx.x * 128 + n_w;

#pragma unroll
    for (int mf = 0; mf < 4; mf++) {
#pragma unroll
        for (int nf = 0; nf < 4; nf++) {
            const int r = row0 + mf * 16 + (lane >> 2);
            const int c = col0 + nf * 8 + (lane & 3) * 2;
            float b0 = 0.f, b1 = 0.f;
            if (EPI == 2 || EPI == 3) { b0 = bias[c]; b1 = bias[c + 1]; }
#pragma unroll
            for (int half = 0; half < 2; half++) {
                const int rr = r + half * 8;
                float v0 = acc[mf][nf][half * 2 + 0];
                float v1 = acc[mf][nf][half * 2 + 1];
                if (EPI == 2) {
                    v0 = roundtf32(gelu_tanh(v0 + b0));
                    v1 = roundtf32(gelu_tanh(v1 + b1));
                }
                if (EPI == 3) { v0 += b0; v1 += b1; }
                if (EPI == 1 || EPI == 3) {
                    const float2 rv = *reinterpret_cast<const float2*>(
                        res + (size_t)rr * N + c);
                    v0 += rv.x; v1 += rv.y;
                }
                float2 o; o.x = v0; o.y = v1;
                *reinterpret_cast<float2*>(C + (size_t)rr * N + c) = o;
            }
        }
    }
}

// ---------------------------------------------------------------------------
// Causal flash attention, fp32 (unchanged except tf32-rounded output:
// y feeds the w_o GEMM as its A operand).
// ---------------------------------------------------------------------------
#define ATT_STRIDE 65
#define ATT_SMEM   (4 * 64 * ATT_STRIDE * (int)sizeof(float))

__global__ __launch_bounds__(256) void attn_kernel(
    const float* __restrict__ qkv,
    float* __restrict__ y)
{
    extern __shared__ float sm[];
    float* Qs = sm;
    float* Ks = Qs + 64 * ATT_STRIDE;
    float* Vs = Ks + 64 * ATT_STRIDE;
    float* Ps = Vs + 64 * ATT_STRIDE;

    const int qt  = blockIdx.x;            // 0..31
    const int bh  = blockIdx.y;            // 0..63
    const int b   = bh >> 4;
    const int h   = bh & 15;
    const int tid = threadIdx.x;
    const int tx  = tid & 15;
    const int ty  = tid >> 4;

    const size_t rstr = 3 * DMODEL;        // qkv row stride
    const float* qbase = qkv + ((size_t)b * SEQ + qt * 64) * rstr + h * HDIM;
    const float* kbase = qkv + (size_t)b * SEQ * rstr + DMODEL     + h * HDIM;
    const float* vbase = qkv + (size_t)b * SEQ * rstr + 2 * DMODEL + h * HDIM;

#pragma unroll
    for (int i = 0; i < 4; i++) {
        int idx = tid + i * 256;
        int r = idx >> 4, c4 = (idx & 15) * 4;
        float4 v = *reinterpret_cast<const float4*>(qbase + (size_t)r * rstr + c4);
        Qs[r * ATT_STRIDE + c4 + 0] = v.x * 0.125f;
        Qs[r * ATT_STRIDE + c4 + 1] = v.y * 0.125f;
        Qs[r * ATT_STRIDE + c4 + 2] = v.z * 0.125f;
        Qs[r * ATT_STRIDE + c4 + 3] = v.w * 0.125f;
    }

    float m[4], l[4], o[4][4];
#pragma unroll
    for (int i = 0; i < 4; i++) {
        m[i] = -1e30f; l[i] = 0.f;
#pragma unroll
        for (int j = 0; j < 4; j++) o[i][j] = 0.f;
    }

    for (int kt = 0; kt <= qt; kt++) {
        __syncthreads();
#pragma unroll
        for (int i = 0; i < 4; i++) {
            int idx = tid + i * 256;
            int r = idx >> 4, c4 = (idx & 15) * 4;
            size_t grow = (size_t)(kt * 64 + r) * rstr + c4;
            float4 kv4 = *reinterpret_cast<const float4*>(kbase + grow);
            Ks[r * ATT_STRIDE + c4 + 0] = kv4.x;
            Ks[r * ATT_STRIDE + c4 + 1] = kv4.y;
            Ks[r * ATT_STRIDE + c4 + 2] = kv4.z;
            Ks[r * ATT_STRIDE + c4 + 3] = kv4.w;
            float4 vv4 = *reinterpret_cast<const float4*>(vbase + grow);
            Vs[r * ATT_STRIDE + c4 + 0] = vv4.x;
            Vs[r * ATT_STRIDE + c4 + 1] = vv4.y;
            Vs[r * ATT_STRIDE + c4 + 2] = vv4.z;
            Vs[r * ATT_STRIDE + c4 + 3] = vv4.w;
        }
        __syncthreads();

        float s[4][4];
#pragma unroll
        for (int i = 0; i < 4; i++)
#pragma unroll
            for (int j = 0; j < 4; j++) s[i][j] = 0.f;
#pragma unroll 8
        for (int k = 0; k < 64; k++) {
            float qr[4], kr[4];
#pragma unroll
            for (int i = 0; i < 4; i++) qr[i] = Qs[(ty * 4 + i) * ATT_STRIDE + k];
#pragma unroll
            for (int j = 0; j < 4; j++) kr[j] = Ks[(tx * 4 + j) * ATT_STRIDE + k];
#pragma unroll
            for (int i = 0; i < 4; i++)
#pragma unroll
                for (int j = 0; j < 4; j++) s[i][j] = fmaf(qr[i], kr[j], s[i][j]);
        }

        if (kt == qt) {
#pragma unroll
            for (int i = 0; i < 4; i++)
#pragma unroll
                for (int j = 0; j < 4; j++)
                    if (tx * 4 + j > ty * 4 + i) s[i][j] = -1e30f;
        }

#pragma unroll
        for (int i = 0; i < 4; i++) {
            float mr = fmaxf(fmaxf(s[i][0], s[i][1]), fmaxf(s[i][2], s[i][3]));
#pragma unroll
            for (int off = 8; off > 0; off >>= 1)
                mr = fmaxf(mr, __shfl_xor_sync(0xffffffffu, mr, off));
            float mn = fmaxf(m[i], mr);
            float corr = __expf(m[i] - mn);
            float psum = 0.f;
#pragma unroll
            for (int j = 0; j < 4; j++) {
                s[i][j] = __expf(s[i][j] - mn);
                psum += s[i][j];
            }
#pragma unroll
            for (int off = 8; off > 0; off >>= 1)
                psum += __shfl_xor_sync(0xffffffffu, psum, off);
            l[i] = l[i] * corr + psum;
            m[i] = mn;
#pragma unroll
            for (int j = 0; j < 4; j++) {
                o[i][j] *= corr;
                Ps[(ty * 4 + i) * ATT_STRIDE + tx * 4 + j] = s[i][j];
            }
        }
        __syncthreads();

#pragma unroll 8
        for (int k = 0; k < 64; k++) {
            float pr[4], vr[4];
#pragma unroll
            for (int i = 0; i < 4; i++) pr[i] = Ps[(ty * 4 + i) * ATT_STRIDE + k];
#pragma unroll
            for (int j = 0; j < 4; j++) vr[j] = Vs[k * ATT_STRIDE + tx * 4 + j];
#pragma unroll
            for (int i = 0; i < 4; i++)
#pragma unroll
                for (int j = 0; j < 4; j++) o[i][j] = fmaf(pr[i], vr[j], o[i][j]);
        }
    }

#pragma unroll
    for (int i = 0; i < 4; i++) {
        float inv = 1.0f / l[i];
        size_t row = (size_t)b * SEQ + qt * 64 + ty * 4 + i;
#pragma unroll
        for (int j = 0; j < 4; j++)
            y[row * DMODEL + h * HDIM + tx * 4 + j] = roundtf32(o[i][j] * inv);
    }
}

// ---------------------------------------------------------------------------
// Launch
// ---------------------------------------------------------------------------
extern "C" void kernel_launch(void* const* d_in, const int* in_sizes, int n_in,
                              void* d_out, int out_size)
{
    const float* x      = (const float*)d_in[0];
    const float* w_attn = (const float*)d_in[1];
    const float* w_o    = (const float*)d_in[2];
    const float* ln1_g  = (const float*)d_in[3];
    const float* ln1_b  = (const float*)d_in[4];
    const float* ln2_g  = (const float*)d_in[5];
    const float* ln2_b  = (const float*)d_in[6];
    const float* w_fc   = (const float*)d_in[7];
    const float* b_fc   = (const float*)d_in[8];
    const float* w_proj = (const float*)d_in[9];
    const float* b_proj = (const float*)d_in[10];
    float* out = (float*)d_out;

    float *ln, *qkvp, *yp, *x1, *hp, *wa, *wo, *wf, *wp;
    cudaGetSymbolAddress((void**)&ln,   g_ln);
    cudaGetSymbolAddress((void**)&qkvp, g_qkv);
    cudaGetSymbolAddress((void**)&yp,   g_y);
    cudaGetSymbolAddress((void**)&x1,   g_x1);
    cudaGetSymbolAddress((void**)&hp,   g_h);
    cudaGetSymbolAddress((void**)&wa,   g_wa);
    cudaGetSymbolAddress((void**)&wo,   g_wo);
    cudaGetSymbolAddress((void**)&wf,   g_wf);
    cudaGetSymbolAddress((void**)&wp,   g_wp);

    cudaFuncSetAttribute(attn_kernel,
                         cudaFuncAttributeMaxDynamicSharedMemorySize, ATT_SMEM);
    cudaFuncSetAttribute(tf32_gemm<0>,
                         cudaFuncAttributeMaxDynamicSharedMemorySize, GEMM_SMEM);
    cudaFuncSetAttribute(tf32_gemm<1>,
                         cudaFuncAttributeMaxDynamicSharedMemorySize, GEMM_SMEM);
    cudaFuncSetAttribute(tf32_gemm<2>,
                         cudaFuncAttributeMaxDynamicSharedMemorySize, GEMM_SMEM);
    cudaFuncSetAttribute(tf32_gemm<3>,
                         cudaFuncAttributeMaxDynamicSharedMemorySize, GEMM_SMEM);

    // 0) pre-round weights to tf32 (rna) — once per launch
    {
        int n;
        n = DMODEL * 3 * DMODEL / 4;
        round_tf32_kernel<<<n / 256, 256>>>(w_attn, wa, n);
        n = DMODEL * DMODEL / 4;
        round_tf32_kernel<<<n / 256, 256>>>(w_o, wo, n);
        n = DMODEL * 4 * DMODEL / 4;
        round_tf32_kernel<<<n / 256, 256>>>(w_fc, wf, n);
        n = 4 * DMODEL * DMODEL / 4;
        round_tf32_kernel<<<n / 256, 256>>>(w_proj, wp, n);
    }

    // 1) ln1 (output tf32-rounded)
    ln_kernel<<<ROWS, 256>>>(x, ln1_g, ln1_b, ln);
    // 2) qkv = ln1 @ w_attn        [8192 x 3072]
    tf32_gemm<0><<<dim3(3 * DMODEL / 128, ROWS / 128), 256, GEMM_SMEM>>>(
        ROWS, 3 * DMODEL, DMODEL, ln, wa, nullptr, nullptr, qkvp);
    // 3) attention -> y (output tf32-rounded)
    attn_kernel<<<dim3(SEQ / 64, BATCH * NHEAD), 256, ATT_SMEM>>>(qkvp, yp);
    // 4) x1 = x + y @ w_o
    tf32_gemm<1><<<dim3(DMODEL / 128, ROWS / 128), 256, GEMM_SMEM>>>(
        ROWS, DMODEL, DMODEL, yp, wo, nullptr, x, x1);
    // 5) ln2 (output tf32-rounded)
    ln_kernel<<<ROWS, 256>>>(x1, ln2_g, ln2_b, ln);
    // 6) h = gelu(ln2 @ w_fc + b_fc)   [8192 x 4096] (output tf32-rounded)
    tf32_gemm<2><<<dim3(4 * DMODEL / 128, ROWS / 128), 256, GEMM_SMEM>>>(
        ROWS, 4 * DMODEL, DMODEL, ln, wf, b_fc, nullptr, hp);
    // 7) out = x1 + h @ w_proj + b_proj
    tf32_gemm<3><<<dim3(DMODEL / 128, ROWS / 128), 256, GEMM_SMEM>>>(
        ROWS, DMODEL, 4 * DMODEL, hp, wp, b_proj, x1, out);
}

// round 7
// speedup vs baseline: 1.4134x; 1.4134x over previous
#include <cuda_runtime.h>
#include <cuda_bf16.h>
#include <math.h>
#include <stdint.h>

// ---------------------------------------------------------------------------
// Problem constants
// ---------------------------------------------------------------------------
#define BATCH 4
#define SEQ   2048
#define DMODEL 1024
#define NHEAD 16
#define HDIM  64
#define ROWS  (BATCH * SEQ)          // 8192
#define EPS   1e-5f

// ---------------------------------------------------------------------------
// Scratch buffers (static device globals: allocation-free per harness rules)
// ---------------------------------------------------------------------------
__device__ float g_ln [ROWS * DMODEL];        // 32 MB  (reused ln1 & ln2)
__device__ float g_qkv[ROWS * 3 * DMODEL];    // 96 MB
__device__ float g_y  [ROWS * DMODEL];        // 32 MB  attention output
__device__ float g_x1 [ROWS * DMODEL];        // 32 MB  residual after attn
__device__ float g_h  [ROWS * 4 * DMODEL];    // 128 MB MLP hidden
// tf32-pre-rounded weights
__device__ float g_wa [DMODEL * 3 * DMODEL];  // 12 MB
__device__ float g_wo [DMODEL * DMODEL];      // 4 MB
__device__ float g_wf [DMODEL * 4 * DMODEL];  // 16 MB
__device__ float g_wp [4 * DMODEL * DMODEL];  // 16 MB

// ---------------------------------------------------------------------------
// tf32 round helper (rna). Result is an fp32 bit pattern with low 13 bits 0.
// ---------------------------------------------------------------------------
__device__ __forceinline__ unsigned f2tf32(float f) {
    unsigned r;
    asm("cvt.rna.tf32.f32 %0, %1;" : "=r"(r) : "f"(f));
    return r;
}
__device__ __forceinline__ float roundtf32(float f) {
    return __uint_as_float(f2tf32(f));
}

// Pre-round a weight matrix to tf32 (once per launch). n4 = #float4 elements.
__global__ __launch_bounds__(256) void round_tf32_kernel(
    const float* __restrict__ in, float* __restrict__ out, int n4)
{
    int i = blockIdx.x * blockDim.x + threadIdx.x;
    if (i < n4) {
        float4 v = reinterpret_cast<const float4*>(in)[i];
        v.x = roundtf32(v.x); v.y = roundtf32(v.y);
        v.z = roundtf32(v.z); v.w = roundtf32(v.w);
        reinterpret_cast<float4*>(out)[i] = v;
    }
}

// ---------------------------------------------------------------------------
// LayerNorm: one block per row (D=1024), 256 threads, float4 per thread.
// Output rounded to tf32 (consumed only by GEMM A operands).
// ---------------------------------------------------------------------------
__device__ __forceinline__ float warp_sum(float v) {
#pragma unroll
    for (int o = 16; o > 0; o >>= 1) v += __shfl_xor_sync(0xffffffffu, v, o);
    return v;
}

__global__ __launch_bounds__(256) void ln_kernel(
    const float* __restrict__ x,
    const float* __restrict__ g,
    const float* __restrict__ b,
    float* __restrict__ out)
{
    const int row = blockIdx.x;
    const int tid = threadIdx.x;
    const float4 v = reinterpret_cast<const float4*>(x + (size_t)row * DMODEL)[tid];

    float s  = v.x + v.y + v.z + v.w;
    float ss = v.x*v.x + v.y*v.y + v.z*v.z + v.w*v.w;
    s  = warp_sum(s);
    ss = warp_sum(ss);

    __shared__ float red0[8], red1[8];
    const int wid = tid >> 5, lane = tid & 31;
    if (lane == 0) { red0[wid] = s; red1[wid] = ss; }
    __syncthreads();
    float ts = 0.f, tss = 0.f;
#pragma unroll
    for (int w = 0; w < 8; w++) { ts += red0[w]; tss += red1[w]; }

    const float mean = ts * (1.0f / DMODEL);
    const float var  = tss * (1.0f / DMODEL) - mean * mean;
    const float rstd = rsqrtf(var + EPS);

    const float4 gv = reinterpret_cast<const float4*>(g)[tid];
    const float4 bv = reinterpret_cast<const float4*>(b)[tid];
    float4 o;
    o.x = roundtf32((v.x - mean) * rstd * gv.x + bv.x);
    o.y = roundtf32((v.y - mean) * rstd * gv.y + bv.y);
    o.z = roundtf32((v.z - mean) * rstd * gv.z + bv.z);
    o.w = roundtf32((v.w - mean) * rstd * gv.w + bv.w);
    reinterpret_cast<float4*>(out + (size_t)row * DMODEL)[tid] = o;
}

// ---------------------------------------------------------------------------
// Shared MMA helpers (validated in the GEMM)
// ---------------------------------------------------------------------------
__device__ __forceinline__ void ldsm4(unsigned& r0, unsigned& r1,
                                      unsigned& r2, unsigned& r3, uint32_t a) {
    asm volatile("ldmatrix.sync.aligned.m8n8.x4.shared.b16 {%0,%1,%2,%3}, [%4];"
                 : "=r"(r0), "=r"(r1), "=r"(r2), "=r"(r3) : "r"(a));
}

__device__ __forceinline__ void mma_tf32(float* c,
                                         unsigned a0, unsigned a1,
                                         unsigned a2, unsigned a3,
                                         unsigned b0, unsigned b1) {
    asm volatile(
        "mma.sync.aligned.m16n8k8.row.col.f32.tf32.tf32.f32 "
        "{%0,%1,%2,%3}, {%4,%5,%6,%7}, {%8,%9}, {%0,%1,%2,%3};"
        : "+f"(c[0]), "+f"(c[1]), "+f"(c[2]), "+f"(c[3])
        : "r"(a0), "r"(a1), "r"(a2), "r"(a3), "r"(b0), "r"(b1));
}

// ---------------------------------------------------------------------------
// TF32 tensor-core GEMM (unchanged from R6)
// ---------------------------------------------------------------------------
__device__ __forceinline__ float gelu_tanh(float x) {
    const float c0 = 0.7978845608028654f;  // sqrt(2/pi)
    const float c1 = 0.044715f;
    float t = tanhf(c0 * (x + c1 * x * x * x));
    return 0.5f * x * (1.0f + t);
}

#define AS_STRIDE 20
#define BS_STRIDE 132
#define A_ELEMS   (128 * AS_STRIDE)
#define B_ELEMS   (16 * BS_STRIDE)
#define GEMM_SMEM (3 * (A_ELEMS + B_ELEMS) * (int)sizeof(float))   // 56064 B

template <int EPI>
__global__ __launch_bounds__(256, 2) void tf32_gemm(
    int M, int N, int K,
    const float* __restrict__ A,
    const float* __restrict__ B,
    const float* __restrict__ bias,
    const float* __restrict__ res,
    float* __restrict__ C)
{
    extern __shared__ float smp[];
    float* sB = smp + 3 * A_ELEMS;
    const uint32_t sA_u = (uint32_t)__cvta_generic_to_shared(smp);
    const uint32_t sB_u = (uint32_t)__cvta_generic_to_shared(sB);

    const int tid  = threadIdx.x;
    const int lane = tid & 31;
    const int wid  = tid >> 5;
    const int m_w  = (wid >> 2) * 64;   // warp M origin (0 or 64)
    const int n_w  = (wid & 3) * 32;    // warp N origin

    const int aRow  = tid >> 2;          // 0..63 (+64 second)
    const int aCol  = (tid & 3) * 4;
    const int bRowK = tid >> 5;          // 0..7  (+8 second)
    const int bColN = (tid & 31) * 4;

    const float* Ag = A + (size_t)(blockIdx.y * 128) * K;
    const float* Bg = B + (size_t)blockIdx.x * 128;

    float acc[4][4][4];
#pragma unroll
    for (int i = 0; i < 4; i++)
#pragma unroll
        for (int j = 0; j < 4; j++)
#pragma unroll
            for (int q = 0; q < 4; q++) acc[i][j][q] = 0.f;

    const int lr  = lane & 7;
    const int lm8 = ((lane >> 3) & 1) * 8;
    const int lc4 = (lane >> 4) * 4;

    const int nk = K >> 4;

#define LOAD_STAGE(KT, ST)                                                        \
    do {                                                                          \
        const float* a0p = Ag + (size_t)aRow * K + (KT) * 16 + aCol;              \
        uint32_t d0 = sA_u + (uint32_t)((ST) * A_ELEMS + aRow * AS_STRIDE + aCol) * 4u; \
        asm volatile("cp.async.cg.shared.global [%0], [%1], 16;"                  \
                     :: "r"(d0), "l"(a0p));                                       \
        asm volatile("cp.async.cg.shared.global [%0], [%1], 16;"                  \
                     :: "r"(d0 + 64u * AS_STRIDE * 4u), "l"(a0p + (size_t)64 * K)); \
        const float* b0p = Bg + (size_t)((KT) * 16 + bRowK) * N + bColN;          \
        uint32_t e0 = sB_u + (uint32_t)((ST) * B_ELEMS + bRowK * BS_STRIDE + bColN) * 4u; \
        asm volatile("cp.async.cg.shared.global [%0], [%1], 16;"                  \
                     :: "r"(e0), "l"(b0p));                                       \
        asm volatile("cp.async.cg.shared.global [%0], [%1], 16;"                  \
                     :: "r"(e0 + 8u * BS_STRIDE * 4u), "l"(b0p + (size_t)8 * N)); \
        asm volatile("cp.async.commit_group;");                                   \
    } while (0)

    LOAD_STAGE(0, 0);
    LOAD_STAGE(1, 1);

    int st = 0, ld = 2;
    for (int kt = 0; kt < nk; kt++) {
        if (kt + 2 < nk) {
            LOAD_STAGE(kt + 2, ld);
            asm volatile("cp.async.wait_group 2;");
        } else if (kt + 1 < nk) {
            asm volatile("cp.async.wait_group 1;");
        } else {
            asm volatile("cp.async.wait_group 0;");
        }
        __syncthreads();

        const uint32_t aBase = sA_u +
            (uint32_t)(st * A_ELEMS + (m_w + lr + lm8) * AS_STRIDE + lc4) * 4u;
        const float* bp = sB + st * B_ELEMS + (lane & 3) * BS_STRIDE
                        + n_w + (lane >> 2);

#pragma unroll
        for (int ks = 0; ks < 2; ks++) {
            const int k8 = ks * 8;
            unsigned afr[4][4];
#pragma unroll
            for (int mf = 0; mf < 4; mf++)
                ldsm4(afr[mf][0], afr[mf][1], afr[mf][2], afr[mf][3],
                      aBase + (uint32_t)(mf * 16 * AS_STRIDE + k8) * 4u);
            unsigned bfr[4][2];
#pragma unroll
            for (int nf = 0; nf < 4; nf++) {
                bfr[nf][0] = __float_as_uint(bp[k8 * BS_STRIDE + nf * 8]);
                bfr[nf][1] = __float_as_uint(bp[(k8 + 4) * BS_STRIDE + nf * 8]);
            }
#pragma unroll
            for (int mf = 0; mf < 4; mf++)
#pragma unroll
                for (int nf = 0; nf < 4; nf++)
                    mma_tf32(acc[mf][nf],
                             afr[mf][0], afr[mf][1], afr[mf][2], afr[mf][3],
                             bfr[nf][0], bfr[nf][1]);
        }
        __syncthreads();
        st++; if (st == 3) st = 0;
        ld++; if (ld == 3) ld = 0;
    }
#undef LOAD_STAGE

    const int row0 = blockIdx.y * 128 + m_w;
    const int col0 = blockIdx.x * 128 + n_w;

#pragma unroll
    for (int mf = 0; mf < 4; mf++) {
#pragma unroll
        for (int nf = 0; nf < 4; nf++) {
            const int r = row0 + mf * 16 + (lane >> 2);
            const int c = col0 + nf * 8 + (lane & 3) * 2;
            float b0 = 0.f, b1 = 0.f;
            if (EPI == 2 || EPI == 3) { b0 = bias[c]; b1 = bias[c + 1]; }
#pragma unroll
            for (int half = 0; half < 2; half++) {
                const int rr = r + half * 8;
                float v0 = acc[mf][nf][half * 2 + 0];
                float v1 = acc[mf][nf][half * 2 + 1];
                if (EPI == 2) {
                    v0 = roundtf32(gelu_tanh(v0 + b0));
                    v1 = roundtf32(gelu_tanh(v1 + b1));
                }
                if (EPI == 3) { v0 += b0; v1 += b1; }
                if (EPI == 1 || EPI == 3) {
                    const float2 rv = *reinterpret_cast<const float2*>(
                        res + (size_t)rr * N + c);
                    v0 += rv.x; v1 += rv.y;
                }
                float2 o; o.x = v0; o.y = v1;
                *reinterpret_cast<float2*>(C + (size_t)rr * N + c) = o;
            }
        }
    }
}

// ---------------------------------------------------------------------------
// Tensor-core causal flash attention (tf32 mma).
// Grid: (qtile 0..15, b*H 0..63). Block: 256 threads = 8 warps.
// Q tile 128 x 64; KV tiles of 64. Warp w owns q rows [16w, 16w+16).
// smem: Qs[128][68], Ks[64][68], Vs[64][68], Ps[128][68]  (102 KB)
//   - stride 68 => conflict-free ldmatrix (rows 4 banks apart)
//   - K kept natural [key][d]: S's B-frag read Ks[key][d] hits 32 distinct banks
// Online softmax on mma C-fragments; P round-trips through Ps (warp-private).
// ---------------------------------------------------------------------------
#define FST 68
#define ATT_SMEM ((128 + 64 + 64 + 128) * FST * (int)sizeof(float))  // 104448

__global__ __launch_bounds__(256) void attn_tc_kernel(
    const float* __restrict__ qkv,
    float* __restrict__ y)
{
    extern __shared__ float sm[];
    float* Qs = sm;                    // [128][FST]
    float* Ks = Qs + 128 * FST;        // [64][FST]   (key, d)
    float* Vs = Ks + 64 * FST;         // [64][FST]   (key, d)
    float* Ps = Vs + 64 * FST;         // [128][FST]
    const uint32_t Qs_u = (uint32_t)__cvta_generic_to_shared(Qs);
    const uint32_t Ps_u = (uint32_t)__cvta_generic_to_shared(Ps);

    const int qt  = blockIdx.x;        // 0..15
    const int bh  = blockIdx.y;        // 0..63
    const int b   = bh >> 4;
    const int h   = bh & 15;
    const int tid = threadIdx.x;
    const int lane = tid & 31;
    const int wid  = tid >> 5;

    const size_t rstr = 3 * DMODEL;
    const float* qbase = qkv + ((size_t)b * SEQ + qt * 128) * rstr + h * HDIM;
    const float* kbase = qkv + (size_t)b * SEQ * rstr + DMODEL     + h * HDIM;
    const float* vbase = qkv + (size_t)b * SEQ * rstr + 2 * DMODEL + h * HDIM;

    // Q tile: scale by 1/sqrt(64), round to tf32
#pragma unroll
    for (int i = 0; i < 8; i++) {
        int idx = tid + i * 256;
        int r = idx >> 4, c4 = (idx & 15) * 4;
        float4 v = *reinterpret_cast<const float4*>(qbase + (size_t)r * rstr + c4);
        Qs[r * FST + c4 + 0] = roundtf32(v.x * 0.125f);
        Qs[r * FST + c4 + 1] = roundtf32(v.y * 0.125f);
        Qs[r * FST + c4 + 2] = roundtf32(v.z * 0.125f);
        Qs[r * FST + c4 + 3] = roundtf32(v.w * 0.125f);
    }

    float m0 = -1e30f, m1 = -1e30f, l0 = 0.f, l1 = 0.f;
    float acc[8][4];
#pragma unroll
    for (int nf = 0; nf < 8; nf++)
#pragma unroll
        for (int q = 0; q < 4; q++) acc[nf][q] = 0.f;

    const int lr  = lane & 7;
    const int lm8 = ((lane >> 3) & 1) * 8;
    const int lc4 = (lane >> 4) * 4;
    const uint32_t aQ = Qs_u + (uint32_t)((wid * 16 + lr + lm8) * FST + lc4) * 4u;
    const uint32_t aP = Ps_u + (uint32_t)((wid * 16 + lr + lm8) * FST + lc4) * 4u;
    const int q0w = qt * 128 + wid * 16;   // warp's first global q row
    const int nkv = 2 * qt + 2;

    for (int kt = 0; kt < nkv; kt++) {
        __syncthreads();   // protect K/V reuse from previous iteration
#pragma unroll
        for (int i = 0; i < 4; i++) {
            int idx = tid + i * 256;
            int r = idx >> 4, c4 = (idx & 15) * 4;
            size_t grow = (size_t)(kt * 64 + r) * rstr + c4;
            float4 k4 = *reinterpret_cast<const float4*>(kbase + grow);
            float4 v4 = *reinterpret_cast<const float4*>(vbase + grow);
            float4 ko, vo;
            ko.x = roundtf32(k4.x); ko.y = roundtf32(k4.y);
            ko.z = roundtf32(k4.z); ko.w = roundtf32(k4.w);
            vo.x = roundtf32(v4.x); vo.y = roundtf32(v4.y);
            vo.z = roundtf32(v4.z); vo.w = roundtf32(v4.w);
            *reinterpret_cast<float4*>(&Ks[r * FST + c4]) = ko;
            *reinterpret_cast<float4*>(&Vs[r * FST + c4]) = vo;
        }
        __syncthreads();

        if (kt * 64 <= q0w + 15) {   // warp not fully masked
            // ---- S = Q @ K^T (warp tile 16x64) ----
            float s[8][4];
#pragma unroll
            for (int nf = 0; nf < 8; nf++)
#pragma unroll
                for (int q = 0; q < 4; q++) s[nf][q] = 0.f;

#pragma unroll
            for (int kk = 0; kk < 8; kk++) {
                unsigned a0, a1, a2, a3;
                ldsm4(a0, a1, a2, a3, aQ + (uint32_t)(kk * 8) * 4u);
#pragma unroll
                for (int nf = 0; nf < 8; nf++) {
                    const float* kp = &Ks[(nf * 8 + (lane >> 2)) * FST
                                          + kk * 8 + (lane & 3)];
                    unsigned b0 = __float_as_uint(kp[0]);
                    unsigned b1 = __float_as_uint(kp[4]);
                    mma_tf32(s[nf], a0, a1, a2, a3, b0, b1);
                }
            }

            // ---- causal mask (diagonal tiles only) ----
            if (kt >= 2 * qt) {
                const int r_lo = q0w + (lane >> 2);
#pragma unroll
                for (int nf = 0; nf < 8; nf++) {
                    int kg = kt * 64 + nf * 8 + 2 * (lane & 3);
                    if (kg     > r_lo)     s[nf][0] = -1e30f;
                    if (kg + 1 > r_lo)     s[nf][1] = -1e30f;
                    if (kg     > r_lo + 8) s[nf][2] = -1e30f;
                    if (kg + 1 > r_lo + 8) s[nf][3] = -1e30f;
                }
            }

            // ---- online softmax (rows lane>>2 and +8; quad shfl reduce) ----
            float mx0 = -1e30f, mx1 = -1e30f;
#pragma unroll
            for (int nf = 0; nf < 8; nf++) {
                mx0 = fmaxf(mx0, fmaxf(s[nf][0], s[nf][1]));
                mx1 = fmaxf(mx1, fmaxf(s[nf][2], s[nf][3]));
            }
            mx0 = fmaxf(mx0, __shfl_xor_sync(0xffffffffu, mx0, 1));
            mx0 = fmaxf(mx0, __shfl_xor_sync(0xffffffffu, mx0, 2));
            mx1 = fmaxf(mx1, __shfl_xor_sync(0xffffffffu, mx1, 1));
            mx1 = fmaxf(mx1, __shfl_xor_sync(0xffffffffu, mx1, 2));

            const float mn0 = fmaxf(m0, mx0);
            const float mn1 = fmaxf(m1, mx1);
            const float cor0 = __expf(m0 - mn0);
            const float cor1 = __expf(m1 - mn1);
            float sum0 = 0.f, sum1 = 0.f;
            const int prow = (wid * 16 + (lane >> 2)) * FST + 2 * (lane & 3);
#pragma unroll
            for (int nf = 0; nf < 8; nf++) {
                float p0 = __expf(s[nf][0] - mn0);
                float p1 = __expf(s[nf][1] - mn0);
                float p2 = __expf(s[nf][2] - mn1);
                float p3 = __expf(s[nf][3] - mn1);
                sum0 += p0 + p1;
                sum1 += p2 + p3;
                float2 w0; w0.x = roundtf32(p0); w0.y = roundtf32(p1);
                float2 w1; w1.x = roundtf32(p2); w1.y = roundtf32(p3);
                *reinterpret_cast<float2*>(&Ps[prow + nf * 8]) = w0;
                *reinterpret_cast<float2*>(&Ps[prow + 8 * FST + nf * 8]) = w1;
            }
            sum0 += __shfl_xor_sync(0xffffffffu, sum0, 1);
            sum0 += __shfl_xor_sync(0xffffffffu, sum0, 2);
            sum1 += __shfl_xor_sync(0xffffffffu, sum1, 1);
            sum1 += __shfl_xor_sync(0xffffffffu, sum1, 2);

            l0 = l0 * cor0 + sum0;
            l1 = l1 * cor1 + sum1;
            m0 = mn0; m1 = mn1;
#pragma unroll
            for (int nf = 0; nf < 8; nf++) {
                acc[nf][0] *= cor0; acc[nf][1] *= cor0;
                acc[nf][2] *= cor1; acc[nf][3] *= cor1;
            }
            __syncwarp();   // Ps visible to ldmatrix across lanes

            // ---- O += P @ V ----
#pragma unroll
            for (int kk = 0; kk < 8; kk++) {
                unsigned a0, a1, a2, a3;
                ldsm4(a0, a1, a2, a3, aP + (uint32_t)(kk * 8) * 4u);
#pragma unroll
                for (int nf = 0; nf < 8; nf++) {
                    const float* vp = &Vs[(kk * 8 + (lane & 3)) * FST
                                          + nf * 8 + (lane >> 2)];
                    unsigned b0 = __float_as_uint(vp[0]);
                    unsigned b1 = __float_as_uint(vp[4 * FST]);
                    mma_tf32(acc[nf], a0, a1, a2, a3, b0, b1);
                }
            }
            __syncwarp();   // PV reads done before next iter's Ps writes
        }
    }

    // ---- normalize + write (tf32-rounded: feeds w_o GEMM A operand) ----
    const float inv0 = 1.0f / l0;
    const float inv1 = 1.0f / l1;
    const size_t row_lo = (size_t)b * SEQ + qt * 128 + wid * 16 + (lane >> 2);
#pragma unroll
    for (int nf = 0; nf < 8; nf++) {
        const int col = h * HDIM + nf * 8 + 2 * (lane & 3);
        float2 o0, o1;
        o0.x = roundtf32(acc[nf][0] * inv0);
        o0.y = roundtf32(acc[nf][1] * inv0);
        o1.x = roundtf32(acc[nf][2] * inv1);
        o1.y = roundtf32(acc[nf][3] * inv1);
        *reinterpret_cast<float2*>(&y[row_lo * DMODEL + col]) = o0;
        *reinterpret_cast<float2*>(&y[(row_lo + 8) * DMODEL + col]) = o1;
    }
}

// ---------------------------------------------------------------------------
// Launch
// ---------------------------------------------------------------------------
extern "C" void kernel_launch(void* const* d_in, const int* in_sizes, int n_in,
                              void* d_out, int out_size)
{
    const float* x      = (const float*)d_in[0];
    const float* w_attn = (const float*)d_in[1];
    const float* w_o    = (const float*)d_in[2];
    const float* ln1_g  = (const float*)d_in[3];
    const float* ln1_b  = (const float*)d_in[4];
    const float* ln2_g  = (const float*)d_in[5];
    const float* ln2_b  = (const float*)d_in[6];
    const float* w_fc   = (const float*)d_in[7];
    const float* b_fc   = (const float*)d_in[8];
    const float* w_proj = (const float*)d_in[9];
    const float* b_proj = (const float*)d_in[10];
    float* out = (float*)d_out;

    float *ln, *qkvp, *yp, *x1, *hp, *wa, *wo, *wf, *wp;
    cudaGetSymbolAddress((void**)&ln,   g_ln);
    cudaGetSymbolAddress((void**)&qkvp, g_qkv);
    cudaGetSymbolAddress((void**)&yp,   g_y);
    cudaGetSymbolAddress((void**)&x1,   g_x1);
    cudaGetSymbolAddress((void**)&hp,   g_h);
    cudaGetSymbolAddress((void**)&wa,   g_wa);
    cudaGetSymbolAddress((void**)&wo,   g_wo);
    cudaGetSymbolAddress((void**)&wf,   g_wf);
    cudaGetSymbolAddress((void**)&wp,   g_wp);

    cudaFuncSetAttribute(attn_tc_kernel,
                         cudaFuncAttributeMaxDynamicSharedMemorySize, ATT_SMEM);
    cudaFuncSetAttribute(tf32_gemm<0>,
                         cudaFuncAttributeMaxDynamicSharedMemorySize, GEMM_SMEM);
    cudaFuncSetAttribute(tf32_gemm<1>,
                         cudaFuncAttributeMaxDynamicSharedMemorySize, GEMM_SMEM);
    cudaFuncSetAttribute(tf32_gemm<2>,
                         cudaFuncAttributeMaxDynamicSharedMemorySize, GEMM_SMEM);
    cudaFuncSetAttribute(tf32_gemm<3>,
                         cudaFuncAttributeMaxDynamicSharedMemorySize, GEMM_SMEM);

    // 0) pre-round weights to tf32 (rna) — once per launch
    {
        int n;
        n = DMODEL * 3 * DMODEL / 4;
        round_tf32_kernel<<<n / 256, 256>>>(w_attn, wa, n);
        n = DMODEL * DMODEL / 4;
        round_tf32_kernel<<<n / 256, 256>>>(w_o, wo, n);
        n = DMODEL * 4 * DMODEL / 4;
        round_tf32_kernel<<<n / 256, 256>>>(w_fc, wf, n);
        n = 4 * DMODEL * DMODEL / 4;
        round_tf32_kernel<<<n / 256, 256>>>(w_proj, wp, n);
    }

    // 1) ln1 (output tf32-rounded)
    ln_kernel<<<ROWS, 256>>>(x, ln1_g, ln1_b, ln);
    // 2) qkv = ln1 @ w_attn        [8192 x 3072]
    tf32_gemm<0><<<dim3(3 * DMODEL / 128, ROWS / 128), 256, GEMM_SMEM>>>(
        ROWS, 3 * DMODEL, DMODEL, ln, wa, nullptr, nullptr, qkvp);
    // 3) attention -> y (tensor-core, output tf32-rounded)
    attn_tc_kernel<<<dim3(SEQ / 128, BATCH * NHEAD), 256, ATT_SMEM>>>(qkvp, yp);
    // 4) x1 = x + y @ w_o
    tf32_gemm<1><<<dim3(DMODEL / 128, ROWS / 128), 256, GEMM_SMEM>>>(
        ROWS, DMODEL, DMODEL, yp, wo, nullptr, x, x1);
    // 5) ln2 (output tf32-rounded)
    ln_kernel<<<ROWS, 256>>>(x1, ln2_g, ln2_b, ln);
    // 6) h = gelu(ln2 @ w_fc + b_fc)   [8192 x 4096] (output tf32-rounded)
    tf32_gemm<2><<<dim3(4 * DMODEL / 128, ROWS / 128), 256, GEMM_SMEM>>>(
        ROWS, 4 * DMODEL, DMODEL, ln, wf, b_fc, nullptr, hp);
    // 7) out = x1 + h @ w_proj + b_proj
    tf32_gemm<3><<<dim3(DMODEL / 128, ROWS / 128), 256, GEMM_SMEM>>>(
        ROWS, DMODEL, 4 * DMODEL, hp, wp, b_proj, x1, out);
}

// round 10
// speedup vs baseline: 2.6114x; 1.8476x over previous
#include <cuda_runtime.h>
#include <cuda_fp16.h>
#include <math.h>
#include <stdint.h>

// ---------------------------------------------------------------------------
// Problem constants
// ---------------------------------------------------------------------------
#define BATCH 4
#define SEQ   2048
#define DMODEL 1024
#define NHEAD 16
#define HDIM  64
#define ROWS  (BATCH * SEQ)          // 8192
#define EPS   1e-5f

// ---------------------------------------------------------------------------
// Scratch buffers (static device globals: allocation-free per harness rules)
// ---------------------------------------------------------------------------
__device__ __half g_lnh[ROWS * DMODEL];       // 16 MB  LN output (fp16, GEMM A)
__device__ float  g_qkv[ROWS * 3 * DMODEL];   // 96 MB  qkv (fp32, attention in)
__device__ __half g_yh [ROWS * DMODEL];       // 16 MB  attention out (fp16)
__device__ float  g_x1 [ROWS * DMODEL];       // 32 MB  residual after attn
__device__ __half g_hh [ROWS * 4 * DMODEL];   // 64 MB  MLP hidden (fp16)
// fp16, TRANSPOSED weights [N][K]
__device__ __half g_wa [3 * DMODEL * DMODEL]; // 6 MB
__device__ __half g_wo [DMODEL * DMODEL];     // 2 MB
__device__ __half g_wf [4 * DMODEL * DMODEL]; // 8 MB
__device__ __half g_wp [DMODEL * 4 * DMODEL]; // 8 MB

// ---------------------------------------------------------------------------
// Helpers
// ---------------------------------------------------------------------------
__device__ __forceinline__ uint32_t smem_u32(const void* p) {
    uint32_t a;
    asm("{ .reg .u64 t; cvta.to.shared.u64 t, %1; cvt.u32.u64 %0, t; }"
        : "=r"(a) : "l"(p));
    return a;
}

#define SMEM_SWIZZLE_128B(off) ((off) ^ (((off) >> 3) & 0x70))

__device__ __forceinline__ unsigned f2tf32(float f) {
    unsigned r;
    asm("cvt.rna.tf32.f32 %0, %1;" : "=r"(r) : "f"(f));
    return r;
}
__device__ __forceinline__ float roundtf32(float f) {
    return __uint_as_float(f2tf32(f));
}

__device__ __forceinline__ void ldsm4(unsigned& r0, unsigned& r1,
                                      unsigned& r2, unsigned& r3, uint32_t a) {
    asm volatile("ldmatrix.sync.aligned.m8n8.x4.shared.b16 {%0,%1,%2,%3}, [%4];"
                 : "=r"(r0), "=r"(r1), "=r"(r2), "=r"(r3) : "r"(a));
}

__device__ __forceinline__ void mma_f16(float* c,
                                        unsigned a0, unsigned a1,
                                        unsigned a2, unsigned a3,
                                        unsigned b0, unsigned b1) {
    asm volatile(
        "mma.sync.aligned.m16n8k16.row.col.f32.f16.f16.f32 "
        "{%0,%1,%2,%3}, {%4,%5,%6,%7}, {%8,%9}, {%0,%1,%2,%3};"
        : "+f"(c[0]), "+f"(c[1]), "+f"(c[2]), "+f"(c[3])
        : "r"(a0), "r"(a1), "r"(a2), "r"(a3), "r"(b0), "r"(b1));
}

__device__ __forceinline__ void mma_tf32(float* c,
                                         unsigned a0, unsigned a1,
                                         unsigned a2, unsigned a3,
                                         unsigned b0, unsigned b1) {
    asm volatile(
        "mma.sync.aligned.m16n8k8.row.col.f32.tf32.tf32.f32 "
        "{%0,%1,%2,%3}, {%4,%5,%6,%7}, {%8,%9}, {%0,%1,%2,%3};"
        : "+f"(c[0]), "+f"(c[1]), "+f"(c[2]), "+f"(c[3])
        : "r"(a0), "r"(a1), "r"(a2), "r"(a3), "r"(b0), "r"(b1));
}

__device__ __forceinline__ float gelu_tanh(float x) {
    const float c0 = 0.7978845608028654f;  // sqrt(2/pi)
    const float c1 = 0.044715f;
    float t = tanhf(c0 * (x + c1 * x * x * x));
    return 0.5f * x * (1.0f + t);
}

// Transpose + fp16-convert a weight matrix: in [K][N] fp32 -> out [N][K] fp16
__global__ __launch_bounds__(256) void transpose_h_kernel(
    const float* __restrict__ in, __half* __restrict__ out, int K, int N)
{
    __shared__ float t[32][33];
    const int n0 = blockIdx.x * 32;
    const int k0 = blockIdx.y * 32;
    const int tx = threadIdx.x, ty = threadIdx.y;
#pragma unroll
    for (int i = 0; i < 4; i++)
        t[ty + 8 * i][tx] = in[(size_t)(k0 + ty + 8 * i) * N + n0 + tx];
    __syncthreads();
#pragma unroll
    for (int i = 0; i < 4; i++)
        out[(size_t)(n0 + ty + 8 * i) * K + k0 + tx] =
            __float2half_rn(t[tx][ty + 8 * i]);
}

// ---------------------------------------------------------------------------
// LayerNorm: fp32 in, fp16 out (consumed only as GEMM A operands)
// ---------------------------------------------------------------------------
__device__ __forceinline__ float warp_sum(float v) {
#pragma unroll
    for (int o = 16; o > 0; o >>= 1) v += __shfl_xor_sync(0xffffffffu, v, o);
    return v;
}

__global__ __launch_bounds__(256) void ln_kernel(
    const float* __restrict__ x,
    const float* __restrict__ g,
    const float* __restrict__ b,
    __half* __restrict__ out)
{
    const int row = blockIdx.x;
    const int tid = threadIdx.x;
    const float4 v = reinterpret_cast<const float4*>(x + (size_t)row * DMODEL)[tid];

    float s  = v.x + v.y + v.z + v.w;
    float ss = v.x*v.x + v.y*v.y + v.z*v.z + v.w*v.w;
    s  = warp_sum(s);
    ss = warp_sum(ss);

    __shared__ float red0[8], red1[8];
    const int wid = tid >> 5, lane = tid & 31;
    if (lane == 0) { red0[wid] = s; red1[wid] = ss; }
    __syncthreads();
    float ts = 0.f, tss = 0.f;
#pragma unroll
    for (int w = 0; w < 8; w++) { ts += red0[w]; tss += red1[w]; }

    const float mean = ts * (1.0f / DMODEL);
    const float var  = tss * (1.0f / DMODEL) - mean * mean;
    const float rstd = rsqrtf(var + EPS);

    const float4 gv = reinterpret_cast<const float4*>(g)[tid];
    const float4 bv = reinterpret_cast<const float4*>(b)[tid];
    __half2 h0 = __floats2half2_rn((v.x - mean) * rstd * gv.x + bv.x,
                                   (v.y - mean) * rstd * gv.y + bv.y);
    __half2 h1 = __floats2half2_rn((v.z - mean) * rstd * gv.z + bv.z,
                                   (v.w - mean) * rstd * gv.w + bv.w);
    __half2* op = reinterpret_cast<__half2*>(out + (size_t)row * DMODEL);
    op[tid * 2 + 0] = h0;
    op[tid * 2 + 1] = h1;
}

// ---------------------------------------------------------------------------
// FP16 tensor-core GEMM: C[M,N] = A[M,K] @ W[K,N], W given transposed fp16
// as Bt[N][K].  CTA tile 128x128, BK=64 (128B/row, SW128 swizzle),
// 256 threads (8 warps as 2x4 -> 64x32 warp tiles), mma.m16n8k16.f16,
// 3-stage cp.async pipeline.  A and B fragments both via ldmatrix.x4.
// EPI: 0 none(f32) | 1 +res(f32) | 2 gelu(acc+bias)->fp16 | 3 +bias+res(f32)
// ---------------------------------------------------------------------------
#define HG_TILE 16384                        // 128 rows x 128 bytes
#define HG_A_OFF(s) ((s) * 2 * HG_TILE)
#define HG_B_OFF(s) ((s) * 2 * HG_TILE + HG_TILE)
#define HG_SMEM (3 * 2 * HG_TILE)            // 98304 B

__device__ __forceinline__ void hg_load_chunk(
    uint32_t smem_base, int stage,
    const __half* __restrict__ Ag, const __half* __restrict__ Bg,
    int K, int c, int tid)
{
    const int kk = c * 64;
#pragma unroll
    for (int i = 0; i < 4; i++) {
        const int L = tid + i * 256;          // 0..1023
        const int row = L >> 3;
        const int unit = L & 7;
        const uint32_t sw = SMEM_SWIZZLE_128B((uint32_t)(row * 128 + unit * 16));
        const __half* ap = Ag + (size_t)row * K + kk + unit * 8;
        const __half* bp = Bg + (size_t)row * K + kk + unit * 8;
        asm volatile("cp.async.cg.shared.global [%0], [%1], 16;"
                     :: "r"(smem_base + HG_A_OFF(stage) + sw), "l"(ap));
        asm volatile("cp.async.cg.shared.global [%0], [%1], 16;"
                     :: "r"(smem_base + HG_B_OFF(stage) + sw), "l"(bp));
    }
    asm volatile("cp.async.commit_group;");
}

template <int EPI>
__global__ __launch_bounds__(256, 2) void h_gemm(
    int M, int N, int K,
    const __half* __restrict__ A,
    const __half* __restrict__ Bt,
    const float* __restrict__ bias,
    const float* __restrict__ res,
    void* __restrict__ Cv)
{
    extern __shared__ char smem[];
    const uint32_t smem_base = smem_u32(smem);

    const int tid  = threadIdx.x;
    const int lane = tid & 31;
    const int wid  = tid >> 5;
    const int m_w  = (wid >> 2) * 64;   // warp M origin (0 or 64)
    const int n_w  = (wid & 3) * 32;    // warp N origin

    const __half* Ag = A  + (size_t)(blockIdx.y * 128) * K;
    const __half* Bg = Bt + (size_t)(blockIdx.x * 128) * K;

    float acc[4][4][4];
#pragma unroll
    for (int i = 0; i < 4; i++)
#pragma unroll
        for (int j = 0; j < 4; j++)
#pragma unroll
            for (int q = 0; q < 4; q++) acc[i][j][q] = 0.f;

    const int lr  = lane & 7;
    const int lm8 = ((lane >> 3) & 1) * 8;
    const int ub  = lane >> 4;                 // 16B unit select (0/1)
    const int rowA = m_w + lr + lm8;           // + mf*16
    const int rowB = n_w + lr + lm8;           // + nt*16

    const int nk = K >> 6;

    hg_load_chunk(smem_base, 0, Ag, Bg, K, 0, tid);
    hg_load_chunk(smem_base, 1, Ag, Bg, K, 1, tid);

    int st = 0, ld = 2;
    for (int c = 0; c < nk; c++) {
        if (c + 2 < nk) {
            hg_load_chunk(smem_base, ld, Ag, Bg, K, c + 2, tid);
            asm volatile("cp.async.wait_group 2;");
        } else if (c + 1 < nk) {
            asm volatile("cp.async.wait_group 1;");
        } else {
            asm volatile("cp.async.wait_group 0;");
        }
        __syncthreads();

        const uint32_t aT = smem_base + HG_A_OFF(st);
        const uint32_t bT = smem_base + HG_B_OFF(st);

#pragma unroll
        for (int ks = 0; ks < 4; ks++) {
            const int u = ks * 2 + ub;
            unsigned av[4][4];
#pragma unroll
            for (int mf = 0; mf < 4; mf++) {
                const uint32_t off = (uint32_t)((rowA + mf * 16) * 128 + u * 16);
                ldsm4(av[mf][0], av[mf][1], av[mf][2], av[mf][3],
                      aT + SMEM_SWIZZLE_128B(off));
            }
            unsigned bv[2][4];
#pragma unroll
            for (int nt = 0; nt < 2; nt++) {
                const uint32_t off = (uint32_t)((rowB + nt * 16) * 128 + u * 16);
                ldsm4(bv[nt][0], bv[nt][1], bv[nt][2], bv[nt][3],
                      bT + SMEM_SWIZZLE_128B(off));
            }
#pragma unroll
            for (int mf = 0; mf < 4; mf++)
#pragma unroll
                for (int nt = 0; nt < 2; nt++) {
                    mma_f16(acc[mf][nt * 2 + 0],
                            av[mf][0], av[mf][1], av[mf][2], av[mf][3],
                            bv[nt][0], bv[nt][2]);
                    mma_f16(acc[mf][nt * 2 + 1],
                            av[mf][0], av[mf][1], av[mf][2], av[mf][3],
                            bv[nt][1], bv[nt][3]);
                }
        }
        __syncthreads();
        st++; if (st == 3) st = 0;
        ld++; if (ld == 3) ld = 0;
    }

    // ---------------- epilogue ----------------
    float*  Cf = (float*)Cv;
    __half* Ch = (__half*)Cv;
    const int row0 = blockIdx.y * 128 + m_w;
    const int col0 = blockIdx.x * 128 + n_w;

#pragma unroll
    for (int mf = 0; mf < 4; mf++) {
#pragma unroll
        for (int nf = 0; nf < 4; nf++) {
            const int r = row0 + mf * 16 + (lane >> 2);
            const int c = col0 + nf * 8 + (lane & 3) * 2;
            float b0 = 0.f, b1 = 0.f;
            if (EPI == 2 || EPI == 3) { b0 = bias[c]; b1 = bias[c + 1]; }
#pragma unroll
            for (int half = 0; half < 2; half++) {
                const int rr = r + half * 8;
                float v0 = acc[mf][nf][half * 2 + 0];
                float v1 = acc[mf][nf][half * 2 + 1];
                if (EPI == 2) {
                    v0 = gelu_tanh(v0 + b0);
                    v1 = gelu_tanh(v1 + b1);
                    *reinterpret_cast<__half2*>(Ch + (size_t)rr * N + c) =
                        __floats2half2_rn(v0, v1);
                } else {
                    if (EPI == 3) { v0 += b0; v1 += b1; }
                    if (EPI == 1 || EPI == 3) {
                        const float2 rv = *reinterpret_cast<const float2*>(
                            res + (size_t)rr * N + c);
                        v0 += rv.x; v1 += rv.y;
                    }
                    float2 o; o.x = v0; o.y = v1;
                    *reinterpret_cast<float2*>(Cf + (size_t)rr * N + c) = o;
                }
            }
        }
    }
}

// ---------------------------------------------------------------------------
// Tensor-core causal flash attention (R7-validated; output now fp16)
// ---------------------------------------------------------------------------
#define FST 68
#define ATT_SMEM ((128 + 64 + 64 + 128) * FST * (int)sizeof(float))  // 104448

__global__ __launch_bounds__(256) void attn_tc_kernel(
    const float* __restrict__ qkv,
    __half* __restrict__ y)
{
    extern __shared__ float sm[];
    float* Qs = sm;                    // [128][FST]
    float* Ks = Qs + 128 * FST;        // [64][FST]
    float* Vs = Ks + 64 * FST;         // [64][FST]
    float* Ps = Vs + 64 * FST;         // [128][FST]
    const uint32_t Qs_u = smem_u32(Qs);
    const uint32_t Ps_u = smem_u32(Ps);

    const int qt  = blockIdx.x;
    const int bh  = blockIdx.y;
    const int b   = bh >> 4;
    const int h   = bh & 15;
    const int tid = threadIdx.x;
    const int lane = tid & 31;
    const int wid  = tid >> 5;

    const size_t rstr = 3 * DMODEL;
    const float* qbase = qkv + ((size_t)b * SEQ + qt * 128) * rstr + h * HDIM;
    const float* kbase = qkv + (size_t)b * SEQ * rstr + DMODEL     + h * HDIM;
    const float* vbase = qkv + (size_t)b * SEQ * rstr + 2 * DMODEL + h * HDIM;

#pragma unroll
    for (int i = 0; i < 8; i++) {
        int idx = tid + i * 256;
        int r = idx >> 4, c4 = (idx & 15) * 4;
        float4 v = *reinterpret_cast<const float4*>(qbase + (size_t)r * rstr + c4);
        Qs[r * FST + c4 + 0] = roundtf32(v.x * 0.125f);
        Qs[r * FST + c4 + 1] = roundtf32(v.y * 0.125f);
        Qs[r * FST + c4 + 2] = roundtf32(v.z * 0.125f);
        Qs[r * FST + c4 + 3] = roundtf32(v.w * 0.125f);
    }

    float m0 = -1e30f, m1 = -1e30f, l0 = 0.f, l1 = 0.f;
    float acc[8][4];
#pragma unroll
    for (int nf = 0; nf < 8; nf++)
#pragma unroll
        for (int q = 0; q < 4; q++) acc[nf][q] = 0.f;

    const int lr  = lane & 7;
    const int lm8 = ((lane >> 3) & 1) * 8;
    const int lc4 = (lane >> 4) * 4;
    const uint32_t aQ = Qs_u + (uint32_t)((wid * 16 + lr + lm8) * FST + lc4) * 4u;
    const uint32_t aP = Ps_u + (uint32_t)((wid * 16 + lr + lm8) * FST + lc4) * 4u;
    const int q0w = qt * 128 + wid * 16;
    const int nkv = 2 * qt + 2;

    for (int kt = 0; kt < nkv; kt++) {
        __syncthreads();
#pragma unroll
        for (int i = 0; i < 4; i++) {
            int idx = tid + i * 256;
            int r = idx >> 4, c4 = (idx & 15) * 4;
            size_t grow = (size_t)(kt * 64 + r) * rstr + c4;
            float4 k4 = *reinterpret_cast<const float4*>(kbase + grow);
            float4 v4 = *reinterpret_cast<const float4*>(vbase + grow);
            float4 ko, vo;
            ko.x = roundtf32(k4.x); ko.y = roundtf32(k4.y);
            ko.z = roundtf32(k4.z); ko.w = roundtf32(k4.w);
            vo.x = roundtf32(v4.x); vo.y = roundtf32(v4.y);
            vo.z = roundtf32(v4.z); vo.w = roundtf32(v4.w);
            *reinterpret_cast<float4*>(&Ks[r * FST + c4]) = ko;
            *reinterpret_cast<float4*>(&Vs[r * FST + c4]) = vo;
        }
        __syncthreads();

        if (kt * 64 <= q0w + 15) {
            float s[8][4];
#pragma unroll
            for (int nf = 0; nf < 8; nf++)
#pragma unroll
                for (int q = 0; q < 4; q++) s[nf][q] = 0.f;

#pragma unroll
            for (int kk = 0; kk < 8; kk++) {
                unsigned a0, a1, a2, a3;
                ldsm4(a0, a1, a2, a3, aQ + (uint32_t)(kk * 8) * 4u);
#pragma unroll
                for (int nf = 0; nf < 8; nf++) {
                    const float* kp = &Ks[(nf * 8 + (lane >> 2)) * FST
                                          + kk * 8 + (lane & 3)];
                    unsigned b0 = __float_as_uint(kp[0]);
                    unsigned b1 = __float_as_uint(kp[4]);
                    mma_tf32(s[nf], a0, a1, a2, a3, b0, b1);
                }
            }

            if (kt >= 2 * qt) {
                const int r_lo = q0w + (lane >> 2);
#pragma unroll
                for (int nf = 0; nf < 8; nf++) {
                    int kg = kt * 64 + nf * 8 + 2 * (lane & 3);
                    if (kg     > r_lo)     s[nf][0] = -1e30f;
                    if (kg + 1 > r_lo)     s[nf][1] = -1e30f;
                    if (kg     > r_lo + 8) s[nf][2] = -1e30f;
                    if (kg + 1 > r_lo + 8) s[nf][3] = -1e30f;
                }
            }

            float mx0 = -1e30f, mx1 = -1e30f;
#pragma unroll
            for (int nf = 0; nf < 8; nf++) {
                mx0 = fmaxf(mx0, fmaxf(s[nf][0], s[nf][1]));
                mx1 = fmaxf(mx1, fmaxf(s[nf][2], s[nf][3]));
            }
            mx0 = fmaxf(mx0, __shfl_xor_sync(0xffffffffu, mx0, 1));
            mx0 = fmaxf(mx0, __shfl_xor_sync(0xffffffffu, mx0, 2));
            mx1 = fmaxf(mx1, __shfl_xor_sync(0xffffffffu, mx1, 1));
            mx1 = fmaxf(mx1, __shfl_xor_sync(0xffffffffu, mx1, 2));

            const float mn0 = fmaxf(m0, mx0);
            const float mn1 = fmaxf(m1, mx1);
            const float cor0 = __expf(m0 - mn0);
            const float cor1 = __expf(m1 - mn1);
            float sum0 = 0.f, sum1 = 0.f;
            const int prow = (wid * 16 + (lane >> 2)) * FST + 2 * (lane & 3);
#pragma unroll
            for (int nf = 0; nf < 8; nf++) {
                float p0 = __expf(s[nf][0] - mn0);
                float p1 = __expf(s[nf][1] - mn0);
                float p2 = __expf(s[nf][2] - mn1);
                float p3 = __expf(s[nf][3] - mn1);
                sum0 += p0 + p1;
                sum1 += p2 + p3;
                float2 w0; w0.x = roundtf32(p0); w0.y = roundtf32(p1);
                float2 w1; w1.x = roundtf32(p2); w1.y = roundtf32(p3);
                *reinterpret_cast<float2*>(&Ps[prow + nf * 8]) = w0;
                *reinterpret_cast<float2*>(&Ps[prow + 8 * FST + nf * 8]) = w1;
            }
            sum0 += __shfl_xor_sync(0xffffffffu, sum0, 1);
            sum0 += __shfl_xor_sync(0xffffffffu, sum0, 2);
            sum1 += __shfl_xor_sync(0xffffffffu, sum1, 1);
            sum1 += __shfl_xor_sync(0xffffffffu, sum1, 2);

            l0 = l0 * cor0 + sum0;
            l1 = l1 * cor1 + sum1;
            m0 = mn0; m1 = mn1;
#pragma unroll
            for (int nf = 0; nf < 8; nf++) {
                acc[nf][0] *= cor0; acc[nf][1] *= cor0;
                acc[nf][2] *= cor1; acc[nf][3] *= cor1;
            }
            __syncwarp();

#pragma unroll
            for (int kk = 0; kk < 8; kk++) {
                unsigned a0, a1, a2, a3;
                ldsm4(a0, a1, a2, a3, aP + (uint32_t)(kk * 8) * 4u);
#pragma unroll
                for (int nf = 0; nf < 8; nf++) {
                    const float* vp = &Vs[(kk * 8 + (lane & 3)) * FST
                                          + nf * 8 + (lane >> 2)];
                    unsigned b0 = __float_as_uint(vp[0]);
                    unsigned b1 = __float_as_uint(vp[4 * FST]);
                    mma_tf32(acc[nf], a0, a1, a2, a3, b0, b1);
                }
            }
            __syncwarp();
        }
    }

    const float inv0 = 1.0f / l0;
    const float inv1 = 1.0f / l1;
    const size_t row_lo = (size_t)b * SEQ + qt * 128 + wid * 16 + (lane >> 2);
#pragma unroll
    for (int nf = 0; nf < 8; nf++) {
        const int col = h * HDIM + nf * 8 + 2 * (lane & 3);
        *reinterpret_cast<__half2*>(&y[row_lo * DMODEL + col]) =
            __floats2half2_rn(acc[nf][0] * inv0, acc[nf][1] * inv0);
        *reinterpret_cast<__half2*>(&y[(row_lo + 8) * DMODEL + col]) =
            __floats2half2_rn(acc[nf][2] * inv1, acc[nf][3] * inv1);
    }
}

// ---------------------------------------------------------------------------
// Launch
// ---------------------------------------------------------------------------
extern "C" void kernel_launch(void* const* d_in, const int* in_sizes, int n_in,
                              void* d_out, int out_size)
{
    const float* x      = (const float*)d_in[0];
    const float* w_attn = (const float*)d_in[1];
    const float* w_o    = (const float*)d_in[2];
    const float* ln1_g  = (const float*)d_in[3];
    const float* ln1_b  = (const float*)d_in[4];
    const float* ln2_g  = (const float*)d_in[5];
    const float* ln2_b  = (const float*)d_in[6];
    const float* w_fc   = (const float*)d_in[7];
    const float* b_fc   = (const float*)d_in[8];
    const float* w_proj = (const float*)d_in[9];
    const float* b_proj = (const float*)d_in[10];
    float* out = (float*)d_out;

    __half *lnh, *yh, *hh, *wa, *wo, *wf, *wp;
    float *qkvp, *x1;
    cudaGetSymbolAddress((void**)&lnh,  g_lnh);
    cudaGetSymbolAddress((void**)&qkvp, g_qkv);
    cudaGetSymbolAddress((void**)&yh,   g_yh);
    cudaGetSymbolAddress((void**)&x1,   g_x1);
    cudaGetSymbolAddress((void**)&hh,   g_hh);
    cudaGetSymbolAddress((void**)&wa,   g_wa);
    cudaGetSymbolAddress((void**)&wo,   g_wo);
    cudaGetSymbolAddress((void**)&wf,   g_wf);
    cudaGetSymbolAddress((void**)&wp,   g_wp);

    cudaFuncSetAttribute(attn_tc_kernel,
                         cudaFuncAttributeMaxDynamicSharedMemorySize, ATT_SMEM);
    cudaFuncSetAttribute(h_gemm<0>,
                         cudaFuncAttributeMaxDynamicSharedMemorySize, HG_SMEM);
    cudaFuncSetAttribute(h_gemm<1>,
                         cudaFuncAttributeMaxDynamicSharedMemorySize, HG_SMEM);
    cudaFuncSetAttribute(h_gemm<2>,
                         cudaFuncAttributeMaxDynamicSharedMemorySize, HG_SMEM);
    cudaFuncSetAttribute(h_gemm<3>,
                         cudaFuncAttributeMaxDynamicSharedMemorySize, HG_SMEM);

    // 0) transpose + fp16-convert weights (once per launch)
    transpose_h_kernel<<<dim3(3 * DMODEL / 32, DMODEL / 32), dim3(32, 8)>>>(
        w_attn, wa, DMODEL, 3 * DMODEL);
    transpose_h_kernel<<<dim3(DMODEL / 32, DMODEL / 32), dim3(32, 8)>>>(
        w_o, wo, DMODEL, DMODEL);
    transpose_h_kernel<<<dim3(4 * DMODEL / 32, DMODEL / 32), dim3(32, 8)>>>(
        w_fc, wf, DMODEL, 4 * DMODEL);
    transpose_h_kernel<<<dim3(DMODEL / 32, 4 * DMODEL / 32), dim3(32, 8)>>>(
        w_proj, wp, 4 * DMODEL, DMODEL);

    // 1) ln1 -> fp16
    ln_kernel<<<ROWS, 256>>>(x, ln1_g, ln1_b, lnh);
    // 2) qkv = ln1 @ w_attn        [8192 x 3072] fp32 out
    h_gemm<0><<<dim3(3 * DMODEL / 128, ROWS / 128), 256, HG_SMEM>>>(
        ROWS, 3 * DMODEL, DMODEL, lnh, wa, nullptr, nullptr, qkvp);
    // 3) attention -> y (fp16)
    attn_tc_kernel<<<dim3(SEQ / 128, BATCH * NHEAD), 256, ATT_SMEM>>>(qkvp, yh);
    // 4) x1 = x + y @ w_o          fp32 out
    h_gemm<1><<<dim3(DMODEL / 128, ROWS / 128), 256, HG_SMEM>>>(
        ROWS, DMODEL, DMODEL, yh, wo, nullptr, x, x1);
    // 5) ln2 -> fp16
    ln_kernel<<<ROWS, 256>>>(x1, ln2_g, ln2_b, lnh);
    // 6) h = gelu(ln2 @ w_fc + b_fc)   [8192 x 4096] fp16 out
    h_gemm<2><<<dim3(4 * DMODEL / 128, ROWS / 128), 256, HG_SMEM>>>(
        ROWS, 4 * DMODEL, DMODEL, lnh, wf, b_fc, nullptr, hh);
    // 7) out = x1 + h @ w_proj + b_proj   fp32 out
    h_gemm<3><<<dim3(DMODEL / 128, ROWS / 128), 256, HG_SMEM>>>(
        ROWS, DMODEL, 4 * DMODEL, hh, wp, b_proj, x1, out);
}